// round 5
// baseline (speedup 1.0000x reference)
#include <cuda_runtime.h>
#include <cuda_bf16.h>

#define N_NODES 100000
#define F 32

__device__ float g_deg[N_NODES];
__device__ float g_dinv[N_NODES];
__device__ float g_hs[N_NODES * F];
__device__ float g_agg[N_NODES * F];
__device__ float g_gmax[F];

// ---------------- degree ----------------
__global__ void k_deg_init(int n) {
    int i = blockIdx.x * blockDim.x + threadIdx.x;
    if (i < n) g_deg[i] = 1.0f;  // self loop
}

__global__ void k_deg_accum(const int* __restrict__ dst, int E) {
    int e = blockIdx.x * blockDim.x + threadIdx.x;
    if (e < E) atomicAdd(&g_deg[__ldg(&dst[e])], 1.0f);
}

// ---------------- layer 1: h = x@W1, hs = h*dinv, agg init = hs ----------------
__global__ void k_h1(const float* __restrict__ x, const float* __restrict__ W1, int n) {
    __shared__ float sW[8 * F];
    int t = threadIdx.x;
    if (t < 8 * F) sW[t] = W1[t];
    __syncthreads();
    int i = blockIdx.x * blockDim.x + t;
    if (i >= n) return;
    float di = rsqrtf(g_deg[i]);
    g_dinv[i] = di;

    float4 a0 = *(const float4*)(x + i * 8);
    float4 a1 = *(const float4*)(x + i * 8 + 4);
    float xv[8] = {a0.x, a0.y, a0.z, a0.w, a1.x, a1.y, a1.z, a1.w};

    float h[F];
#pragma unroll
    for (int j = 0; j < F; j++) h[j] = 0.f;
#pragma unroll
    for (int k = 0; k < 8; k++) {
        float xk = xv[k];
#pragma unroll
        for (int j = 0; j < F; j++) h[j] = fmaf(xk, sW[k * F + j], h[j]);
    }
    float4* hp = (float4*)(g_hs + i * F);
    float4* ap = (float4*)(g_agg + i * F);
#pragma unroll
    for (int q = 0; q < F / 4; q++) {
        float4 v = make_float4(h[q*4+0]*di, h[q*4+1]*di, h[q*4+2]*di, h[q*4+3]*di);
        hp[q] = v;
        ap[q] = v;
    }
}

// ---------------- scatter: agg[dst] += hs[src], one warp per edge ----------------
__global__ void k_scatter(const int* __restrict__ src,
                          const int* __restrict__ dst, int E) {
    unsigned int t = blockIdx.x * blockDim.x + threadIdx.x;
    unsigned int e = t >> 5;
    int lane = t & 31;
    if (e >= (unsigned int)E) return;
    int s = __ldg(&src[e]);
    int d = __ldg(&dst[e]);
    atomicAdd(&g_agg[d * F + lane], __ldg(&g_hs[s * F + lane]));
}

// ---------------- layer 2: a = relu(dinv*agg+b1); h2 = a@W2; hs/agg = h2*dinv ----------------
__global__ void k_h2(const float* __restrict__ W2, const float* __restrict__ b1, int n) {
    __shared__ float sW[F * F];
    __shared__ float sb[F];
    int t = threadIdx.x;
    for (int k = t; k < F * F; k += blockDim.x) sW[k] = W2[k];
    if (t < F) sb[t] = b1[t];
    if (blockIdx.x == 0 && t < F) g_gmax[t] = 0.f;  // reset pool accumulator (runs before k_final)
    __syncthreads();
    int i = blockIdx.x * blockDim.x + t;
    if (i >= n) return;
    float di = g_dinv[i];

    float a[F];
    const float4* gp = (const float4*)(g_agg + i * F);
#pragma unroll
    for (int q = 0; q < F / 4; q++) {
        float4 v = gp[q];
        a[q*4+0] = fmaxf(fmaf(di, v.x, sb[q*4+0]), 0.f);
        a[q*4+1] = fmaxf(fmaf(di, v.y, sb[q*4+1]), 0.f);
        a[q*4+2] = fmaxf(fmaf(di, v.z, sb[q*4+2]), 0.f);
        a[q*4+3] = fmaxf(fmaf(di, v.w, sb[q*4+3]), 0.f);
    }
    float h[F];
#pragma unroll
    for (int j = 0; j < F; j++) h[j] = 0.f;
#pragma unroll
    for (int k = 0; k < F; k++) {
        float ak = a[k];
#pragma unroll
        for (int j = 0; j < F; j++) h[j] = fmaf(ak, sW[k * F + j], h[j]);
    }
    float4* hp = (float4*)(g_hs + i * F);
    float4* ap = (float4*)(g_agg + i * F);
#pragma unroll
    for (int q = 0; q < F / 4; q++) {
        float4 v = make_float4(h[q*4+0]*di, h[q*4+1]*di, h[q*4+2]*di, h[q*4+3]*di);
        hp[q] = v;
        ap[q] = v;
    }
}

// ---------------- final: relu + global max pool ----------------
__global__ void k_final(const float* __restrict__ b2, int n) {
    __shared__ float sb[F];
    __shared__ int smax[F];
    int t = threadIdx.x;
    if (t < F) { sb[t] = b2[t]; smax[t] = 0; }
    __syncthreads();
    int i = blockIdx.x * blockDim.x + t;

    float v[F];
    if (i < n) {
        float di = g_dinv[i];
        const float4* gp = (const float4*)(g_agg + i * F);
#pragma unroll
        for (int q = 0; q < F / 4; q++) {
            float4 w = gp[q];
            v[q*4+0] = fmaxf(fmaf(di, w.x, sb[q*4+0]), 0.f);
            v[q*4+1] = fmaxf(fmaf(di, w.y, sb[q*4+1]), 0.f);
            v[q*4+2] = fmaxf(fmaf(di, w.z, sb[q*4+2]), 0.f);
            v[q*4+3] = fmaxf(fmaf(di, w.w, sb[q*4+3]), 0.f);
        }
    } else {
#pragma unroll
        for (int j = 0; j < F; j++) v[j] = 0.f;
    }
    // warp-level max per feature (ReLU output >= 0 -> int compare valid)
#pragma unroll
    for (int o = 16; o > 0; o >>= 1) {
#pragma unroll
        for (int j = 0; j < F; j++)
            v[j] = fmaxf(v[j], __shfl_xor_sync(0xFFFFFFFFu, v[j], o));
    }
    if ((t & 31) == 0) {
#pragma unroll
        for (int j = 0; j < F; j++) atomicMax(&smax[j], __float_as_int(v[j]));
    }
    __syncthreads();
    if (t < F) atomicMax((int*)&g_gmax[t], smax[t]);
}

// ---------------- head: g@fcW + fcb, log_softmax ----------------
__global__ void k_head(const float* __restrict__ fcW, const float* __restrict__ fcb,
                       float* __restrict__ out) {
    if (threadIdx.x != 0) return;
    float g[F];
#pragma unroll
    for (int j = 0; j < F; j++) g[j] = g_gmax[j];
    float lg[5];
#pragma unroll
    for (int c = 0; c < 5; c++) lg[c] = fcb[c];
    for (int j = 0; j < F; j++) {
        float gj = g[j];
#pragma unroll
        for (int c = 0; c < 5; c++) lg[c] = fmaf(gj, fcW[j * 5 + c], lg[c]);
    }
    float m = lg[0];
#pragma unroll
    for (int c = 1; c < 5; c++) m = fmaxf(m, lg[c]);
    float s = 0.f;
#pragma unroll
    for (int c = 0; c < 5; c++) s += expf(lg[c] - m);
    float ls = logf(s) + m;
#pragma unroll
    for (int c = 0; c < 5; c++) out[c] = lg[c] - ls;
}

extern "C" void kernel_launch(void* const* d_in, const int* in_sizes, int n_in,
                              void* d_out, int out_size) {
    const float* x   = (const float*)d_in[0];
    const int*   ei  = (const int*)d_in[1];   // jnp "int64" is int32 (x64 disabled)
    const float* W1  = (const float*)d_in[2];
    const float* b1  = (const float*)d_in[3];
    const float* W2  = (const float*)d_in[4];
    const float* b2  = (const float*)d_in[5];
    const float* fcW = (const float*)d_in[6];
    const float* fcb = (const float*)d_in[7];

    int n = in_sizes[0] / 8;
    int E = in_sizes[1] / 2;
    const int* src = ei;
    const int* dst = ei + E;

    int nb = (n + 255) / 256;
    int eb = (E + 255) / 256;
    unsigned int sb = (unsigned int)(((long long)E * F + 255) / 256);

    k_deg_init<<<nb, 256>>>(n);
    k_deg_accum<<<eb, 256>>>(dst, E);
    k_h1<<<nb, 256>>>(x, W1, n);
    k_scatter<<<sb, 256>>>(src, dst, E);
    k_h2<<<nb, 256>>>(W2, b1, n);
    k_scatter<<<sb, 256>>>(src, dst, E);
    k_final<<<nb, 256>>>(b2, n);
    k_head<<<1, 32>>>(fcW, fcb, (float*)d_out);
}

// round 9
// speedup vs baseline: 1.9702x; 1.9702x over previous
#include <cuda_runtime.h>
#include <cuda_bf16.h>

#define N_NODES 100000
#define F 32

__device__ float g_deg[N_NODES];
__device__ float g_dinv[N_NODES];
__device__ float g_hs[N_NODES * F];
__device__ float g_agg[N_NODES * F];
__device__ float g_gmax[F];

// ---------------- degree ----------------
__global__ void k_deg_init(int n) {
    int i = blockIdx.x * blockDim.x + threadIdx.x;
    if (i < n) g_deg[i] = 1.0f;  // self loop
}

__global__ void k_deg_accum(const int* __restrict__ dst, int E) {
    int e = blockIdx.x * blockDim.x + threadIdx.x;
    if (e < E) atomicAdd(&g_deg[__ldg(&dst[e])], 1.0f);
}

// ---------------- layer 1: h = x@W1, hs = h*dinv, agg init = hs ----------------
__global__ void k_h1(const float* __restrict__ x, const float* __restrict__ W1, int n) {
    __shared__ float sW[8 * F];
    int t = threadIdx.x;
    if (t < 8 * F) sW[t] = W1[t];
    __syncthreads();
    int i = blockIdx.x * blockDim.x + t;
    if (i >= n) return;
    float di = rsqrtf(g_deg[i]);
    g_dinv[i] = di;

    float4 a0 = *(const float4*)(x + i * 8);
    float4 a1 = *(const float4*)(x + i * 8 + 4);
    float xv[8] = {a0.x, a0.y, a0.z, a0.w, a1.x, a1.y, a1.z, a1.w};

    float h[F];
#pragma unroll
    for (int j = 0; j < F; j++) h[j] = 0.f;
#pragma unroll
    for (int k = 0; k < 8; k++) {
        float xk = xv[k];
#pragma unroll
        for (int j = 0; j < F; j++) h[j] = fmaf(xk, sW[k * F + j], h[j]);
    }
    float4* hp = (float4*)(g_hs + i * F);
    float4* ap = (float4*)(g_agg + i * F);
#pragma unroll
    for (int q = 0; q < F / 4; q++) {
        float4 v = make_float4(h[q*4+0]*di, h[q*4+1]*di, h[q*4+2]*di, h[q*4+3]*di);
        hp[q] = v;
        ap[q] = v;
    }
}

// ---------------- scatter: agg[dst] += hs[src], 8 lanes per edge, v4 red ----------------
__global__ void k_scatter(const int* __restrict__ src,
                          const int* __restrict__ dst, int E) {
    unsigned int t = blockIdx.x * blockDim.x + threadIdx.x;
    unsigned int e = t >> 3;          // 8 lanes per edge (F/4 = 8 float4 chunks)
    int q = (t & 7) << 2;             // float offset of this lane's chunk
    if (e >= (unsigned int)E) return;
    int s = __ldg(&src[e]);
    int d = __ldg(&dst[e]);
    const float4 v = *(const float4*)(g_hs + s * F + q);
    float* p = g_agg + d * F + q;
    asm volatile("red.global.add.v4.f32 [%0], {%1,%2,%3,%4};"
                 :: "l"(p), "f"(v.x), "f"(v.y), "f"(v.z), "f"(v.w)
                 : "memory");
}

// ---------------- layer 2: a = relu(dinv*agg+b1); h2 = a@W2; hs/agg = h2*dinv ----------------
__global__ void k_h2(const float* __restrict__ W2, const float* __restrict__ b1, int n) {
    __shared__ float sW[F * F];
    __shared__ float sb[F];
    int t = threadIdx.x;
    for (int k = t; k < F * F; k += blockDim.x) sW[k] = W2[k];
    if (t < F) sb[t] = b1[t];
    if (blockIdx.x == 0 && t < F) g_gmax[t] = 0.f;  // reset pool accumulator (runs before k_final)
    __syncthreads();
    int i = blockIdx.x * blockDim.x + t;
    if (i >= n) return;
    float di = g_dinv[i];

    float a[F];
    const float4* gp = (const float4*)(g_agg + i * F);
#pragma unroll
    for (int q = 0; q < F / 4; q++) {
        float4 v = gp[q];
        a[q*4+0] = fmaxf(fmaf(di, v.x, sb[q*4+0]), 0.f);
        a[q*4+1] = fmaxf(fmaf(di, v.y, sb[q*4+1]), 0.f);
        a[q*4+2] = fmaxf(fmaf(di, v.z, sb[q*4+2]), 0.f);
        a[q*4+3] = fmaxf(fmaf(di, v.w, sb[q*4+3]), 0.f);
    }
    float h[F];
#pragma unroll
    for (int j = 0; j < F; j++) h[j] = 0.f;
#pragma unroll
    for (int k = 0; k < F; k++) {
        float ak = a[k];
#pragma unroll
        for (int j = 0; j < F; j++) h[j] = fmaf(ak, sW[k * F + j], h[j]);
    }
    float4* hp = (float4*)(g_hs + i * F);
    float4* ap = (float4*)(g_agg + i * F);
#pragma unroll
    for (int q = 0; q < F / 4; q++) {
        float4 v = make_float4(h[q*4+0]*di, h[q*4+1]*di, h[q*4+2]*di, h[q*4+3]*di);
        hp[q] = v;
        ap[q] = v;
    }
}

// ---------------- final: relu + global max pool ----------------
__global__ void k_final(const float* __restrict__ b2, int n) {
    __shared__ float sb[F];
    __shared__ int smax[F];
    int t = threadIdx.x;
    if (t < F) { sb[t] = b2[t]; smax[t] = 0; }
    __syncthreads();
    int i = blockIdx.x * blockDim.x + t;

    float v[F];
    if (i < n) {
        float di = g_dinv[i];
        const float4* gp = (const float4*)(g_agg + i * F);
#pragma unroll
        for (int q = 0; q < F / 4; q++) {
            float4 w = gp[q];
            v[q*4+0] = fmaxf(fmaf(di, w.x, sb[q*4+0]), 0.f);
            v[q*4+1] = fmaxf(fmaf(di, w.y, sb[q*4+1]), 0.f);
            v[q*4+2] = fmaxf(fmaf(di, w.z, sb[q*4+2]), 0.f);
            v[q*4+3] = fmaxf(fmaf(di, w.w, sb[q*4+3]), 0.f);
        }
    } else {
#pragma unroll
        for (int j = 0; j < F; j++) v[j] = 0.f;
    }
    // warp-level max per feature (ReLU output >= 0 -> int compare valid)
#pragma unroll
    for (int o = 16; o > 0; o >>= 1) {
#pragma unroll
        for (int j = 0; j < F; j++)
            v[j] = fmaxf(v[j], __shfl_xor_sync(0xFFFFFFFFu, v[j], o));
    }
    if ((t & 31) == 0) {
#pragma unroll
        for (int j = 0; j < F; j++) atomicMax(&smax[j], __float_as_int(v[j]));
    }
    __syncthreads();
    if (t < F) atomicMax((int*)&g_gmax[t], smax[t]);
}

// ---------------- head: g@fcW + fcb, log_softmax ----------------
__global__ void k_head(const float* __restrict__ fcW, const float* __restrict__ fcb,
                       float* __restrict__ out) {
    if (threadIdx.x != 0) return;
    float g[F];
#pragma unroll
    for (int j = 0; j < F; j++) g[j] = g_gmax[j];
    float lg[5];
#pragma unroll
    for (int c = 0; c < 5; c++) lg[c] = fcb[c];
    for (int j = 0; j < F; j++) {
        float gj = g[j];
#pragma unroll
        for (int c = 0; c < 5; c++) lg[c] = fmaf(gj, fcW[j * 5 + c], lg[c]);
    }
    float m = lg[0];
#pragma unroll
    for (int c = 1; c < 5; c++) m = fmaxf(m, lg[c]);
    float s = 0.f;
#pragma unroll
    for (int c = 0; c < 5; c++) s += expf(lg[c] - m);
    float ls = logf(s) + m;
#pragma unroll
    for (int c = 0; c < 5; c++) out[c] = lg[c] - ls;
}

extern "C" void kernel_launch(void* const* d_in, const int* in_sizes, int n_in,
                              void* d_out, int out_size) {
    const float* x   = (const float*)d_in[0];
    const int*   ei  = (const int*)d_in[1];   // jnp "int64" is int32 (x64 disabled)
    const float* W1  = (const float*)d_in[2];
    const float* b1  = (const float*)d_in[3];
    const float* W2  = (const float*)d_in[4];
    const float* b2  = (const float*)d_in[5];
    const float* fcW = (const float*)d_in[6];
    const float* fcb = (const float*)d_in[7];

    int n = in_sizes[0] / 8;
    int E = in_sizes[1] / 2;
    const int* src = ei;
    const int* dst = ei + E;

    int nb = (n + 255) / 256;
    int eb = (E + 255) / 256;
    unsigned int sb = (unsigned int)(((long long)E * (F / 4) + 255) / 256);

    k_deg_init<<<nb, 256>>>(n);
    k_deg_accum<<<eb, 256>>>(dst, E);
    k_h1<<<nb, 256>>>(x, W1, n);
    k_scatter<<<sb, 256>>>(src, dst, E);
    k_h2<<<nb, 256>>>(W2, b1, n);
    k_scatter<<<sb, 256>>>(src, dst, E);
    k_final<<<nb, 256>>>(b2, n);
    k_head<<<1, 32>>>(fcW, fcb, (float*)d_out);
}